// round 5
// baseline (speedup 1.0000x reference)
#include <cuda_runtime.h>

// DWT1D bior3.5, J=3, fused single kernel. One row per CTA, chain in smem.
//   level1: 16384 -> lo1(8197), hi1(8197)
//   level2: lo1   -> lo2(4104), hi2(4104)
//   level3: lo2   -> lo3(2057), hi3(2057)
// Output: [x0(=lo3) | hi1 | hi2 | hi3], rows concatenated per section.
//
// lo[n] = sum_l s[2n-10+l] * h0[l]   (zero extension; odd-pad == zero ext)
// h1[i] = (i even ? -1 : +1) * h0[11-i]
//
// R4 changes vs R0:
//  - 1024 threads/CTA (32 warps/SM; was 16) -> issue-bound fix
//  - SW128-style XOR swizzle on all smem (16B units): kills the 2-way LDS.128
//    and 4-way STS.32 bank conflicts caused by the 128B lane stride
//  - lo written to smem as one swizzled STS.128 instead of 4 STS.32

#define N_IN   16384
#define O1     8197
#define O2     4104
#define O3     2057
#define NROWS  1024

// Padded sizes: cover max fast-path read (base+19) AND multiple of 32 floats
// so the swizzle (which permutes within 32-float rows) stays in-bounds.
#define SX_PAD   16416   // valid [0,16384), zeros [16384,16416)
#define SL1_PAD  8224    // valid [0,8197),  zeros [8197,8224)
#define SL2_PAD  4128    // valid [0,4104),  zeros [4104,4128)
#define SMEM_FLOATS (SX_PAD + SL1_PAD + SL2_PAD)   // 28768 floats = 115072 B

#define OFF_X0  0
#define OFF_H1  ((size_t)NROWS * O3)
#define OFF_H2  (OFF_H1 + (size_t)NROWS * O1)
#define OFF_H3  (OFF_H2 + (size_t)NROWS * O2)

// Swizzle on 16-byte (float4) unit index: XOR bits[3:5] into bits[0:2].
// Permutes within each 32-float block; bijection when array size % 32 == 0.
__device__ __forceinline__ int swz4(int u) { return u ^ ((u >> 3) & 7); }
// Swizzle for a scalar float index.
__device__ __forceinline__ int swzf(int f) {
    int u = f >> 2;
    return (swz4(u) << 2) | (f & 3);
}

// One analysis level. Thread computes 4 consecutive output pairs n0=4t..4t+3
// from s[8t-12 .. 8t+7] via 5 swizzled LDS.128. Groups t<2 take the checked
// scalar path (only idx>=0 needs checking at the left edge).
__device__ __forceinline__ void run_level(
    const float* __restrict__ s, int M,
    const float* __restrict__ h0, const float* __restrict__ h1,
    float* __restrict__ lo_smem,   // may be nullptr
    float* __restrict__ lo_gmem,   // may be nullptr
    float* __restrict__ hi_gmem)
{
    const float4* s4 = (const float4*)s;
    const int ngroups = (M + 3) >> 2;
    for (int t = threadIdx.x; t < ngroups; t += blockDim.x) {
        const int n0 = 4 * t;
        float lo[4] = {0.f, 0.f, 0.f, 0.f};
        float hi[4] = {0.f, 0.f, 0.f, 0.f};

        if (t >= 2) {
            const int ub = 2 * t - 3;          // (8t-12)/4
            float v[20];
            #pragma unroll
            for (int q = 0; q < 5; q++) {
                float4 a = s4[swz4(ub + q)];
                v[4 * q + 0] = a.x; v[4 * q + 1] = a.y;
                v[4 * q + 2] = a.z; v[4 * q + 3] = a.w;
            }
            #pragma unroll
            for (int j = 0; j < 4; j++) {
                #pragma unroll
                for (int l = 0; l < 12; l++) {
                    const float xv = v[2 + 2 * j + l];
                    lo[j] += xv * h0[l];
                    hi[j] += xv * h1[l];
                }
            }
        } else {
            #pragma unroll
            for (int j = 0; j < 4; j++) {
                const int n = n0 + j;
                #pragma unroll
                for (int l = 0; l < 12; l++) {
                    const int idx = 2 * n - 10 + l;
                    if (idx >= 0) {
                        const float xv = s[swzf(idx)];
                        lo[j] += xv * h0[l];
                        hi[j] += xv * h1[l];
                    }
                }
            }
        }

        // lo -> smem: single swizzled STS.128. The only overflow case is
        // level 1, t=2049 (n=8197..8199): those windows lie entirely in the
        // zero pad, so the computed values are exactly 0 and land in the
        // zero-filled pad region — safe unconditionally.
        if (lo_smem)
            ((float4*)lo_smem)[swz4(t)] = make_float4(lo[0], lo[1], lo[2], lo[3]);

        #pragma unroll
        for (int j = 0; j < 4; j++) {
            const int n = n0 + j;
            if (n < M) {
                hi_gmem[n] = hi[j];
                if (lo_gmem) lo_gmem[n] = lo[j];
            }
        }
    }
}

__global__ void __launch_bounds__(1024, 1)
dwt1d_fused_kernel(const float* __restrict__ x,
                   const float* __restrict__ hac,
                   float* __restrict__ out)
{
    extern __shared__ float sm[];
    float* sx  = sm;
    float* sl1 = sm + SX_PAD;
    float* sl2 = sm + SX_PAD + SL1_PAD;

    const int row = blockIdx.x;
    const float* xr = x + (size_t)row * N_IN;

    // Filters -> registers (QMF pair derived from h0).
    float h0[12], h1[12];
    #pragma unroll
    for (int i = 0; i < 12; i++) h0[i] = __ldg(hac + i);
    #pragma unroll
    for (int i = 0; i < 12; i++)
        h1[i] = ((i & 1) ? 1.0f : -1.0f) * h0[11 - i];

    // Load input row into swizzled smem (coalesced LDG.128 -> conflict-free
    // swizzled STS.128: consecutive u stay in distinct banks under swz4).
    {
        const float4* in4 = (const float4*)xr;
        float4* sx4 = (float4*)sx;
        for (int i = threadIdx.x; i < N_IN / 4; i += blockDim.x)
            sx4[swz4(i)] = in4[i];
    }

    // Zero-fill padding tails (through the swizzle).
    {
        const int tid = threadIdx.x;
        if (tid < 32)                      sx [swzf(N_IN + tid)]      = 0.f; // 32
        else if (tid >= 32 && tid < 59)    sl1[swzf(O1 + (tid - 32))] = 0.f; // 27
        else if (tid >= 64 && tid < 88)    sl2[swzf(O2 + (tid - 64))] = 0.f; // 24
    }
    __syncthreads();

    float* hi1 = out + OFF_H1 + (size_t)row * O1;
    float* hi2 = out + OFF_H2 + (size_t)row * O2;
    float* hi3 = out + OFF_H3 + (size_t)row * O3;
    float* x0  = out + OFF_X0 + (size_t)row * O3;

    run_level(sx,  O1, h0, h1, sl1,     nullptr, hi1);
    __syncthreads();
    run_level(sl1, O2, h0, h1, sl2,     nullptr, hi2);
    __syncthreads();
    run_level(sl2, O3, h0, h1, nullptr, x0,      hi3);
}

extern "C" void kernel_launch(void* const* d_in, const int* in_sizes, int n_in,
                              void* d_out, int out_size)
{
    // metadata order: x (16*64*16384), hac (12). Guard against swap.
    int xi = 0, hi = 1;
    if (n_in >= 2 && in_sizes[0] == 12) { xi = 1; hi = 0; }

    const float* x   = (const float*)d_in[xi];
    const float* hac = (const float*)d_in[hi];
    float* out = (float*)d_out;

    const size_t smem_bytes = (size_t)SMEM_FLOATS * sizeof(float);
    cudaFuncSetAttribute(dwt1d_fused_kernel,
                         cudaFuncAttributeMaxDynamicSharedMemorySize,
                         (int)smem_bytes);

    dwt1d_fused_kernel<<<NROWS, 1024, smem_bytes>>>(x, hac, out);
}